// round 1
// baseline (speedup 1.0000x reference)
#include <cuda_runtime.h>
#include <cuda_bf16.h>
#include <math.h>

// Problem constants (fixed by setup_inputs)
#define Bq   8
#define Nn   1024
#define INF_ 64
#define HID  256
#define OUTD 128
#define Hh   4
#define D1   (HID/Hh)   // 64
#define D2   (OUTD/Hh)  // 32
#define NEG_SLOPE 0.2f

// ---------------- scratch (device globals; no allocations) ----------------
__device__ float     d_g1[Bq*Nn*HID];      // 8 MB  : layer1 projected features
__device__ float     d_h1[Bq*Nn*HID];      // 8 MB  : layer1 output (relu)
__device__ float     d_g2[Bq*Nn*OUTD];     // 4 MB  : layer2 projected features
__device__ float     d_Wf[INF_*HID];       // fused Wp@W1
__device__ float     d_bf[HID];            // bp@W1
__device__ float     d_invn[Nn];
__device__ unsigned  d_maskbits[Nn*(Nn/32)];
__device__ int       d_nbr[Nn*Nn];         // 4 MB CSR (fixed row stride Nn)
__device__ int       d_deg[Nn];
__device__ float     d_asrc1[Bq*Nn*Hh], d_adst1[Bq*Nn*Hh];
__device__ float     d_asrc2[Bq*Nn*Hh], d_adst2[Bq*Nn*Hh];

// ---------------- kernel 1: row inverse norms of embed ----------------
__global__ void invnorm_kernel(const float* __restrict__ embed) {
    __shared__ float s[HID];
    int i = blockIdx.x, t = threadIdx.x;
    float e = embed[i*HID + t];
    s[t] = e * e;
    __syncthreads();
    for (int st = HID/2; st > 0; st >>= 1) {
        if (t < st) s[t] += s[t + st];
        __syncthreads();
    }
    if (t == 0) d_invn[i] = rsqrtf(s[0]);
}

// ---------------- kernel 2: mask bits  (ne@ne.T > 0.5) ----------------
// block (32,32), grid (N/32, N/32); tile GEMM over K=HID
__global__ void mask_kernel(const float* __restrict__ embed) {
    __shared__ float Ei[32][33];
    __shared__ float Ej[32][33];
    int tx = threadIdx.x, ty = threadIdx.y;
    int i = blockIdx.y*32 + ty;
    int j = blockIdx.x*32 + tx;
    float acc = 0.f;
    for (int k0 = 0; k0 < HID; k0 += 32) {
        Ei[ty][tx] = embed[(blockIdx.y*32 + ty)*HID + k0 + tx];
        Ej[ty][tx] = embed[(blockIdx.x*32 + ty)*HID + k0 + tx];
        __syncthreads();
        #pragma unroll
        for (int kk = 0; kk < 32; kk++)
            acc += Ei[ty][kk] * Ej[tx][kk];
        __syncthreads();
    }
    float sim = acc * d_invn[i] * d_invn[j];
    unsigned word = __ballot_sync(0xFFFFFFFFu, sim > 0.5f);
    if (tx == 0) d_maskbits[i*(Nn/32) + blockIdx.x] = word;
}

// ---------------- kernel 3: build CSR neighbor lists (ordered, deterministic) ----
__global__ void csr_kernel() {
    int i = blockIdx.x*blockDim.x + threadIdx.x;
    if (i >= Nn) return;
    int deg = 0;
    #pragma unroll 4
    for (int w = 0; w < Nn/32; w++) {
        unsigned word = d_maskbits[i*(Nn/32) + w];
        while (word) {
            int b = __ffs(word) - 1;
            word &= word - 1;
            d_nbr[i*Nn + deg++] = w*32 + b;
        }
    }
    d_deg[i] = deg;
}

// ---------------- generic fp32 tiled GEMM: C = A[MxK] @ B[KxN] (+bias) ------
#define BM 64
#define BN 64
#define BK 16
__global__ void gemm_kernel(const float* __restrict__ A, const float* __restrict__ Bm,
                            const float* __restrict__ bias, float* __restrict__ Cm,
                            int M, int N, int K) {
    __shared__ float As[BK][BM + 1];
    __shared__ float Bs[BK][BN + 1];
    int tid = threadIdx.x;            // 256
    int tx = tid & 15, ty = tid >> 4; // 16x16
    int row0 = blockIdx.y * BM, col0 = blockIdx.x * BN;
    float acc[4][4] = {};
    for (int k0 = 0; k0 < K; k0 += BK) {
        for (int idx = tid; idx < BM*BK; idx += 256) {
            int r = idx / BK, kk = idx % BK;
            int gr = row0 + r, gk = k0 + kk;
            As[kk][r] = (gr < M && gk < K) ? A[(size_t)gr*K + gk] : 0.f;
        }
        for (int idx = tid; idx < BK*BN; idx += 256) {
            int kk = idx / BN, c = idx % BN;
            int gc = col0 + c, gk = k0 + kk;
            Bs[kk][c] = (gk < K && gc < N) ? Bm[(size_t)gk*N + gc] : 0.f;
        }
        __syncthreads();
        #pragma unroll
        for (int kk = 0; kk < BK; kk++) {
            float ra[4], rb[4];
            #pragma unroll
            for (int u = 0; u < 4; u++) ra[u] = As[kk][ty*4 + u];
            #pragma unroll
            for (int u = 0; u < 4; u++) rb[u] = Bs[kk][tx*4 + u];
            #pragma unroll
            for (int a = 0; a < 4; a++)
                #pragma unroll
                for (int b = 0; b < 4; b++)
                    acc[a][b] += ra[a] * rb[b];
        }
        __syncthreads();
    }
    #pragma unroll
    for (int a = 0; a < 4; a++) {
        int r = row0 + ty*4 + a;
        if (r >= M) continue;
        #pragma unroll
        for (int b = 0; b < 4; b++) {
            int c = col0 + tx*4 + b;
            if (c < N)
                Cm[(size_t)r*N + c] = acc[a][b] + (bias ? bias[c] : 0.f);
        }
    }
}

// ---------------- bfused = bp @ W1 (tiny) ----------------
__global__ void bfused_kernel(const float* __restrict__ bp, const float* __restrict__ W1) {
    int c = threadIdx.x;
    float s = 0.f;
    for (int k = 0; k < HID; k++) s += bp[k] * W1[k*HID + c];
    d_bf[c] = s;
}

// ---------------- per-row src/dst attention logits ----------------
// asrc[row,h] = sum_d g[row, h*D+d]*a_src[h*D+d]; same for adst.
template <int C, int Dd>
__global__ void srcdst_kernel(const float* __restrict__ g,
                              const float* __restrict__ a_src,
                              const float* __restrict__ a_dst,
                              float* __restrict__ asrc,
                              float* __restrict__ adst) {
    __shared__ float ss[C], sd[C];
    int row = blockIdx.x, c = threadIdx.x;
    float gv = g[(size_t)row*C + c];
    ss[c] = gv * a_src[c];
    sd[c] = gv * a_dst[c];
    __syncthreads();
    for (int st = Dd/2; st > 0; st >>= 1) {
        if ((c & (Dd-1)) < st) { ss[c] += ss[c+st]; sd[c] += sd[c+st]; }
        __syncthreads();
    }
    if ((c & (Dd-1)) == 0) {
        int h = c / Dd;
        asrc[row*Hh + h] = ss[c];
        adst[row*Hh + h] = sd[c];
    }
}

// ---------------- sparse GAT attention (one block per (b,i) row) ----------------
// out[row, c] = (sum_{j in nbr(i)} softmax_j(lrelu(adst_i+asrc_j)) * g[b,j,c]) + bias[c]
template <int C, int Dd, bool RELU>
__global__ void attn_kernel(const float* __restrict__ g,
                            const float* __restrict__ asrc,
                            const float* __restrict__ adst,
                            const float* __restrict__ bias,
                            float* __restrict__ out) {
    __shared__ int   snbr[Nn];
    __shared__ float sw[Nn*Hh];
    __shared__ float sadst[Hh], sm[Hh], srZ[Hh];
    int row = blockIdx.x;
    int b = row >> 10;            // row / N
    int i = row & (Nn-1);
    int tid = threadIdx.x;
    int deg = d_deg[i];
    for (int k = tid; k < deg; k += C) snbr[k] = d_nbr[i*Nn + k];
    if (tid < Hh) sadst[tid] = adst[row*Hh + tid];
    __syncthreads();
    for (int idx = tid; idx < deg*Hh; idx += C) {
        int k = idx >> 2, h = idx & 3;
        float v = sadst[h] + asrc[(b*Nn + snbr[k])*Hh + h];
        sw[idx] = (v >= 0.f) ? v : NEG_SLOPE * v;
    }
    __syncthreads();
    if (tid < Hh) {
        float m = -1e30f;
        for (int k = 0; k < deg; k++) m = fmaxf(m, sw[k*Hh + tid]);
        float Z = 0.f;
        for (int k = 0; k < deg; k++) {
            float p = expf(sw[k*Hh + tid] - m);
            sw[k*Hh + tid] = p;   // overwrite with prob numerator
            Z += p;
        }
        srZ[tid] = 1.f / Z;
        sm[tid] = m;
    }
    __syncthreads();
    int h = tid / Dd;
    float acc = 0.f;
    if (deg > 0) {
        for (int k = 0; k < deg; k++)
            acc += sw[k*Hh + h] * g[(size_t)(b*Nn + snbr[k])*C + tid];
        acc *= srZ[h];
    } else {
        // all-masked row: reference softmax degenerates to uniform over all j
        for (int j = 0; j < Nn; j++)
            acc += g[(size_t)(b*Nn + j)*C + tid];
        acc *= (1.f / Nn);
    }
    float o = acc + bias[tid];
    if (RELU) o = fmaxf(o, 0.f);
    out[(size_t)row*C + tid] = o;
}

// ---------------- launch ----------------
extern "C" void kernel_launch(void* const* d_in, const int* in_sizes, int n_in,
                              void* d_out, int out_size) {
    const float* x      = (const float*)d_in[0];
    const float* embed  = (const float*)d_in[1];
    const float* Wp     = (const float*)d_in[2];
    const float* bp     = (const float*)d_in[3];
    const float* W1     = (const float*)d_in[4];
    const float* a_src1 = (const float*)d_in[5];
    const float* a_dst1 = (const float*)d_in[6];
    const float* b1     = (const float*)d_in[7];
    const float* W2     = (const float*)d_in[8];
    const float* a_src2 = (const float*)d_in[9];
    const float* a_dst2 = (const float*)d_in[10];
    const float* b2     = (const float*)d_in[11];
    float* out = (float*)d_out;

    float *g1, *h1, *g2, *Wf, *asrc1p, *adst1p, *asrc2p, *adst2p;
    cudaGetSymbolAddress((void**)&g1, d_g1);
    cudaGetSymbolAddress((void**)&h1, d_h1);
    cudaGetSymbolAddress((void**)&g2, d_g2);
    cudaGetSymbolAddress((void**)&Wf, d_Wf);
    cudaGetSymbolAddress((void**)&asrc1p, d_asrc1);
    cudaGetSymbolAddress((void**)&adst1p, d_adst1);
    cudaGetSymbolAddress((void**)&asrc2p, d_asrc2);
    cudaGetSymbolAddress((void**)&adst2p, d_adst2);
    float* bf;
    cudaGetSymbolAddress((void**)&bf, d_bf);

    const int M = Bq * Nn;   // 8192

    // adjacency
    invnorm_kernel<<<Nn, HID>>>(embed);
    mask_kernel<<<dim3(Nn/32, Nn/32), dim3(32, 32)>>>(embed);
    csr_kernel<<<4, 256>>>();

    // fused projection: Wf = Wp@W1, bf = bp@W1, g1 = x@Wf + bf
    gemm_kernel<<<dim3((HID+BN-1)/BN, (INF_+BM-1)/BM), 256>>>(Wp, W1, nullptr, Wf, INF_, HID, HID);
    bfused_kernel<<<1, HID>>>(bp, W1);
    gemm_kernel<<<dim3(HID/BN, M/BM), 256>>>(x, Wf, bf, g1, M, HID, INF_);

    // layer 1
    srcdst_kernel<HID, D1><<<M, HID>>>(g1, a_src1, a_dst1, asrc1p, adst1p);
    attn_kernel<HID, D1, true><<<M, HID>>>(g1, asrc1p, adst1p, b1, h1);

    // layer 2
    gemm_kernel<<<dim3(OUTD/BN, M/BM), 256>>>(h1, W2, nullptr, g2, M, OUTD, HID);
    srcdst_kernel<OUTD, D2><<<M, OUTD>>>(g2, a_src2, a_dst2, asrc2p, adst2p);
    attn_kernel<OUTD, D2, false><<<M, OUTD>>>(g2, asrc2p, adst2p, b2, out);
}

// round 3
// speedup vs baseline: 2.0508x; 2.0508x over previous
#include <cuda_runtime.h>
#include <cuda_bf16.h>
#include <math.h>

// Problem constants (fixed by setup_inputs)
#define Bq   8
#define Nn   1024
#define INF_ 64
#define HID  256
#define OUTD 128
#define Hh   4
#define D1   (HID/Hh)   // 64
#define D2   (OUTD/Hh)  // 32
#define NEG_SLOPE 0.2f

// ---------------- scratch (device globals; no allocations) ----------------
__device__ float     d_g1[Bq*Nn*HID];      // 8 MB  : layer1 projected features
__device__ float     d_h1[Bq*Nn*HID];      // 8 MB  : layer1 output (relu)
__device__ float     d_g2[Bq*Nn*OUTD];     // 4 MB  : layer2 projected features
__device__ float     d_Wf[INF_*HID];       // fused Wp@W1
__device__ float     d_bf[HID];            // bp@W1
__device__ float     d_invn[Nn];
__device__ unsigned  d_maskbits[Nn*(Nn/32)];
__device__ int       d_nbr[Nn*Nn];         // 4 MB CSR (fixed row stride Nn)
__device__ int       d_deg[Nn];
__device__ float     d_asrc1[Bq*Nn*Hh], d_adst1[Bq*Nn*Hh];
__device__ float     d_asrc2[Bq*Nn*Hh], d_adst2[Bq*Nn*Hh];

// ---------------- kernel 1: row inverse norms of embed ----------------
__global__ void invnorm_kernel(const float* __restrict__ embed) {
    __shared__ float s[HID];
    int i = blockIdx.x, t = threadIdx.x;
    float e = embed[i*HID + t];
    s[t] = e * e;
    __syncthreads();
    for (int st = HID/2; st > 0; st >>= 1) {
        if (t < st) s[t] += s[t + st];
        __syncthreads();
    }
    if (t == 0) d_invn[i] = rsqrtf(s[0]);
}

// ---------------- kernel 2: symmetric mask bits (ne@ne.T > 0.5) ----------------
// 64x64 tile per block, only upper-triangular (bx>=by) tiles; mirror-write.
// 256 threads, 4x4 microtile.
__global__ __launch_bounds__(256) void mask_kernel(const float* __restrict__ embed) {
    // decode triangular block index -> (by=q, bx=p) with p>=q
    int id = blockIdx.x;
    int p = (int)((sqrtf(8.f*(float)id + 1.f) - 1.f) * 0.5f);
    while ((p+1)*(p+2)/2 <= id) p++;
    while (p*(p+1)/2 > id) p--;
    int q = id - p*(p+1)/2;
    int by = q, bx = p;
    int i0 = by*64, j0 = bx*64;

    __shared__ float Ei[16][64];
    __shared__ float Ej[16][64];
    __shared__ unsigned sbA[64][2];
    __shared__ unsigned sbB[64][2];

    int tid = threadIdx.x;
    int tx = tid & 15, ty = tid >> 4;
    if (tid < 128) { sbA[tid>>1][tid&1] = 0u; sbB[tid>>1][tid&1] = 0u; }

    float acc[4][4] = {};
    int lr = tid >> 2, lkq = tid & 3;   // loader mapping: 64 rows x 4 float4
    for (int k0 = 0; k0 < HID; k0 += 16) {
        float4 v = *(const float4*)(embed + (size_t)(i0+lr)*HID + k0 + lkq*4);
        Ei[lkq*4+0][lr] = v.x; Ei[lkq*4+1][lr] = v.y;
        Ei[lkq*4+2][lr] = v.z; Ei[lkq*4+3][lr] = v.w;
        float4 w = *(const float4*)(embed + (size_t)(j0+lr)*HID + k0 + lkq*4);
        Ej[lkq*4+0][lr] = w.x; Ej[lkq*4+1][lr] = w.y;
        Ej[lkq*4+2][lr] = w.z; Ej[lkq*4+3][lr] = w.w;
        __syncthreads();
        #pragma unroll
        for (int kk = 0; kk < 16; kk++) {
            float4 av = *(float4*)&Ei[kk][ty*4];
            float4 bv = *(float4*)&Ej[kk][tx*4];
            float ra[4] = {av.x, av.y, av.z, av.w};
            float rb[4] = {bv.x, bv.y, bv.z, bv.w};
            #pragma unroll
            for (int a = 0; a < 4; a++)
                #pragma unroll
                for (int b = 0; b < 4; b++)
                    acc[a][b] += ra[a] * rb[b];
        }
        __syncthreads();
    }

    float invi[4], invj[4];
    #pragma unroll
    for (int a = 0; a < 4; a++) invi[a] = d_invn[i0 + ty*4 + a];
    #pragma unroll
    for (int b = 0; b < 4; b++) invj[b] = d_invn[j0 + tx*4 + b];

    bool bit[4][4];
    #pragma unroll
    for (int a = 0; a < 4; a++)
        #pragma unroll
        for (int b = 0; b < 4; b++)
            bit[a][b] = (acc[a][b] * invi[a] * invj[b]) > 0.5f;

    #pragma unroll
    for (int a = 0; a < 4; a++) {
        unsigned m = 0;
        #pragma unroll
        for (int b = 0; b < 4; b++) if (bit[a][b]) m |= (1u << b);
        if (m) atomicOr(&sbA[ty*4+a][(tx*4) >> 5], m << ((tx*4) & 31));
    }
    #pragma unroll
    for (int b = 0; b < 4; b++) {
        unsigned m = 0;
        #pragma unroll
        for (int a = 0; a < 4; a++) if (bit[a][b]) m |= (1u << a);
        if (m) atomicOr(&sbB[tx*4+b][(ty*4) >> 5], m << ((ty*4) & 31));
    }
    __syncthreads();

    if (tid < 128) {
        int r = tid >> 1, w = tid & 1;
        d_maskbits[(size_t)(i0+r)*(Nn/32) + (j0>>5) + w] = sbA[r][w];
        if (bx != by)
            d_maskbits[(size_t)(j0+r)*(Nn/32) + (i0>>5) + w] = sbB[r][w];
    }
}

// ---------------- kernel 3: build CSR neighbor lists (ordered, deterministic) ----
__global__ void csr_kernel() {
    int i = blockIdx.x*blockDim.x + threadIdx.x;
    if (i >= Nn) return;
    int deg = 0;
    #pragma unroll 4
    for (int w = 0; w < Nn/32; w++) {
        unsigned word = d_maskbits[i*(Nn/32) + w];
        while (word) {
            int b = __ffs(word) - 1;
            word &= word - 1;
            d_nbr[i*Nn + deg++] = w*32 + b;
        }
    }
    d_deg[i] = deg;
}

// ---------------- Wf = Wp@W1 (+ bias row bf = bp@W1) ----------------
// one block per output row; Wp row staged in smem; W1 streamed (L2 resident).
__global__ __launch_bounds__(HID) void wf_kernel(const float* __restrict__ Wp,
                                                 const float* __restrict__ bp,
                                                 const float* __restrict__ W1) {
    __shared__ float srow[HID];
    int r = blockIdx.x, c = threadIdx.x;
    const float* src = (r < INF_) ? (Wp + (size_t)r*HID) : bp;
    srow[c] = src[c];
    __syncthreads();
    float acc = 0.f;
    #pragma unroll 8
    for (int k = 0; k < HID; k++)
        acc += srow[k] * W1[(size_t)k*HID + c];
    if (r < INF_) d_Wf[(size_t)r*HID + c] = acc;
    else          d_bf[c] = acc;
}

// ---------------- fp32 tiled GEMM: C = A[MxK] @ B[KxN] (+bias) ------
// 128x64 block tile, 8x4 microtile, 256 threads, float4 everywhere.
// Requires M%128==0, N%64==0, K%16==0 (true for all call sites).
#define BM 128
#define BN 64
#define BK 16
__global__ __launch_bounds__(256) void gemm_kernel(const float* __restrict__ A,
                                                   const float* __restrict__ Bm,
                                                   const float* __restrict__ bias,
                                                   float* __restrict__ Cm,
                                                   int M, int N, int K) {
    __shared__ float As[BK][BM];
    __shared__ float Bs[BK][BN];
    int tid = threadIdx.x;
    int tx = tid & 15, ty = tid >> 4;
    int row0 = blockIdx.y * BM, col0 = blockIdx.x * BN;

    float acc[8][4] = {};

    for (int k0 = 0; k0 < K; k0 += BK) {
        #pragma unroll
        for (int i = 0; i < 2; i++) {
            int idx = tid*2 + i;
            int r = idx >> 2, kq = idx & 3;
            float4 v = *(const float4*)(A + (size_t)(row0 + r)*K + k0 + kq*4);
            As[kq*4+0][r] = v.x; As[kq*4+1][r] = v.y;
            As[kq*4+2][r] = v.z; As[kq*4+3][r] = v.w;
        }
        {
            int kk = tid >> 4, cq = tid & 15;
            *(float4*)&Bs[kk][cq*4] =
                *(const float4*)(Bm + (size_t)(k0+kk)*N + col0 + cq*4);
        }
        __syncthreads();
        #pragma unroll
        for (int kk = 0; kk < BK; kk++) {
            float4 a0 = *(float4*)&As[kk][ty*8];
            float4 a1 = *(float4*)&As[kk][ty*8+4];
            float4 b0 = *(float4*)&Bs[kk][tx*4];
            float ra[8] = {a0.x,a0.y,a0.z,a0.w,a1.x,a1.y,a1.z,a1.w};
            float rb[4] = {b0.x,b0.y,b0.z,b0.w};
            #pragma unroll
            for (int a = 0; a < 8; a++)
                #pragma unroll
                for (int b = 0; b < 4; b++)
                    acc[a][b] += ra[a] * rb[b];
        }
        __syncthreads();
    }

    float4 bv = make_float4(0.f, 0.f, 0.f, 0.f);
    if (bias) bv = *(const float4*)(bias + col0 + tx*4);
    #pragma unroll
    for (int a = 0; a < 8; a++) {
        int r = row0 + ty*8 + a;
        float4 o;
        o.x = acc[a][0] + bv.x;
        o.y = acc[a][1] + bv.y;
        o.z = acc[a][2] + bv.z;
        o.w = acc[a][3] + bv.w;
        *(float4*)(Cm + (size_t)r*N + col0 + tx*4) = o;
    }
}

// ---------------- per-row src/dst attention logits ----------------
template <int C, int Dd>
__global__ void srcdst_kernel(const float* __restrict__ g,
                              const float* __restrict__ a_src,
                              const float* __restrict__ a_dst,
                              float* __restrict__ asrc,
                              float* __restrict__ adst) {
    __shared__ float ss[C], sd[C];
    int row = blockIdx.x, c = threadIdx.x;
    float gv = g[(size_t)row*C + c];
    ss[c] = gv * a_src[c];
    sd[c] = gv * a_dst[c];
    __syncthreads();
    for (int st = Dd/2; st > 0; st >>= 1) {
        if ((c & (Dd-1)) < st) { ss[c] += ss[c+st]; sd[c] += sd[c+st]; }
        __syncthreads();
    }
    if ((c & (Dd-1)) == 0) {
        int h = c / Dd;
        asrc[row*Hh + h] = ss[c];
        adst[row*Hh + h] = sd[c];
    }
}

// ---------------- sparse GAT attention (one block per (b,i) row) ----------------
template <int C, int Dd, bool RELU>
__global__ void attn_kernel(const float* __restrict__ g,
                            const float* __restrict__ asrc,
                            const float* __restrict__ adst,
                            const float* __restrict__ bias,
                            float* __restrict__ out) {
    __shared__ int   snbr[Nn];
    __shared__ float sw[Nn*Hh];
    __shared__ float sadst[Hh], srZ[Hh];
    int row = blockIdx.x;
    int b = row >> 10;            // row / N
    int i = row & (Nn-1);
    int tid = threadIdx.x;
    int deg = d_deg[i];
    for (int k = tid; k < deg; k += C) snbr[k] = d_nbr[i*Nn + k];
    if (tid < Hh) sadst[tid] = adst[row*Hh + tid];
    __syncthreads();
    for (int idx = tid; idx < deg*Hh; idx += C) {
        int k = idx >> 2, h = idx & 3;
        float v = sadst[h] + asrc[(b*Nn + snbr[k])*Hh + h];
        sw[idx] = (v >= 0.f) ? v : NEG_SLOPE * v;
    }
    __syncthreads();
    if (tid < Hh) {
        float m = -1e30f;
        for (int k = 0; k < deg; k++) m = fmaxf(m, sw[k*Hh + tid]);
        float Z = 0.f;
        for (int k = 0; k < deg; k++) {
            float p = expf(sw[k*Hh + tid] - m);
            sw[k*Hh + tid] = p;
            Z += p;
        }
        srZ[tid] = 1.f / Z;
    }
    __syncthreads();
    int h = tid / Dd;
    float acc = 0.f;
    if (deg > 0) {
        for (int k = 0; k < deg; k++)
            acc += sw[k*Hh + h] * g[(size_t)(b*Nn + snbr[k])*C + tid];
        acc *= srZ[h];
    } else {
        for (int j = 0; j < Nn; j++)
            acc += g[(size_t)(b*Nn + j)*C + tid];
        acc *= (1.f / Nn);
    }
    float o = acc + bias[tid];
    if (RELU) o = fmaxf(o, 0.f);
    out[(size_t)row*C + tid] = o;
}

// ---------------- launch ----------------
extern "C" void kernel_launch(void* const* d_in, const int* in_sizes, int n_in,
                              void* d_out, int out_size) {
    const float* x      = (const float*)d_in[0];
    const float* embed  = (const float*)d_in[1];
    const float* Wp     = (const float*)d_in[2];
    const float* bp     = (const float*)d_in[3];
    const float* W1     = (const float*)d_in[4];
    const float* a_src1 = (const float*)d_in[5];
    const float* a_dst1 = (const float*)d_in[6];
    const float* b1     = (const float*)d_in[7];
    const float* W2     = (const float*)d_in[8];
    const float* a_src2 = (const float*)d_in[9];
    const float* a_dst2 = (const float*)d_in[10];
    const float* b2     = (const float*)d_in[11];
    float* out = (float*)d_out;

    float *g1, *h1, *g2, *Wf, *bf, *asrc1p, *adst1p, *asrc2p, *adst2p;
    cudaGetSymbolAddress((void**)&g1, d_g1);
    cudaGetSymbolAddress((void**)&h1, d_h1);
    cudaGetSymbolAddress((void**)&g2, d_g2);
    cudaGetSymbolAddress((void**)&Wf, d_Wf);
    cudaGetSymbolAddress((void**)&bf, d_bf);
    cudaGetSymbolAddress((void**)&asrc1p, d_asrc1);
    cudaGetSymbolAddress((void**)&adst1p, d_adst1);
    cudaGetSymbolAddress((void**)&asrc2p, d_asrc2);
    cudaGetSymbolAddress((void**)&adst2p, d_adst2);

    const int M = Bq * Nn;   // 8192

    // fused projection weights (independent of adjacency)
    wf_kernel<<<INF_ + 1, HID>>>(Wp, bp, W1);

    // adjacency
    invnorm_kernel<<<Nn, HID>>>(embed);
    mask_kernel<<<(Nn/64)*((Nn/64)+1)/2, 256>>>(embed);   // 136 triangular tiles
    csr_kernel<<<4, 256>>>();

    // g1 = x @ Wf + bf
    gemm_kernel<<<dim3(HID/BN, M/BM), 256>>>(x, Wf, bf, g1, M, HID, INF_);

    // layer 1
    srcdst_kernel<HID, D1><<<M, HID>>>(g1, a_src1, a_dst1, asrc1p, adst1p);
    attn_kernel<HID, D1, true><<<M, HID>>>(g1, asrc1p, adst1p, b1, h1);

    // layer 2
    gemm_kernel<<<dim3(OUTD/BN, M/BM), 256>>>(h1, W2, nullptr, g2, M, OUTD, HID);
    srcdst_kernel<OUTD, D2><<<M, OUTD>>>(g2, a_src2, a_dst2, asrc2p, adst2p);
    attn_kernel<OUTD, D2, false><<<M, OUTD>>>(g2, asrc2p, adst2p, b2, out);
}

// round 7
// speedup vs baseline: 2.3147x; 1.1287x over previous
#include <cuda_runtime.h>
#include <cuda_bf16.h>
#include <math.h>

// Problem constants (fixed by setup_inputs)
#define Bq   8
#define Nn   1024
#define INF_ 64
#define HID  256
#define OUTD 128
#define Hh   4
#define D1   (HID/Hh)   // 64
#define D2   (OUTD/Hh)  // 32
#define NEG_SLOPE 0.2f

// ---------------- scratch (device globals; no allocations) ----------------
__device__ float     d_g1[Bq*Nn*HID];      // 8 MB
__device__ float     d_h1[Bq*Nn*HID];      // 8 MB
__device__ float     d_g2[Bq*Nn*OUTD];     // 4 MB
__device__ float     d_Wf[INF_*HID];
__device__ float     d_bf[HID];
__device__ float     d_invn[Nn];
__device__ unsigned  d_maskbits[Nn*(Nn/32)];
__device__ int       d_nbr[Nn*Nn];         // 4 MB CSR (fixed row stride Nn)
__device__ int       d_deg[Nn];
__device__ float     d_asrc1[Bq*Nn*Hh], d_adst1[Bq*Nn*Hh];
__device__ float     d_asrc2[Bq*Nn*Hh], d_adst2[Bq*Nn*Hh];

// ---------------- kernel 1: row inverse norms of embed ----------------
__global__ void invnorm_kernel(const float* __restrict__ embed) {
    __shared__ float s[HID];
    int i = blockIdx.x, t = threadIdx.x;
    float e = embed[i*HID + t];
    s[t] = e * e;
    __syncthreads();
    for (int st = HID/2; st > 0; st >>= 1) {
        if (t < st) s[t] += s[t + st];
        __syncthreads();
    }
    if (t == 0) d_invn[i] = rsqrtf(s[0]);
}

// ---------------- kernel 2: symmetric mask bits (ne@ne.T > 0.5) ----------------
__global__ __launch_bounds__(256) void mask_kernel(const float* __restrict__ embed) {
    // decode triangular block index -> (by=q, bx=p) with p>=q
    int id = blockIdx.x;
    int p = (int)((sqrtf(8.f*(float)id + 1.f) - 1.f) * 0.5f);
    while ((p+1)*(p+2)/2 <= id) p++;
    while (p*(p+1)/2 > id) p--;
    int q = id - p*(p+1)/2;
    int by = q, bx = p;
    int i0 = by*64, j0 = bx*64;

    __shared__ float Ei[16][64];
    __shared__ float Ej[16][64];
    __shared__ unsigned sbA[64][2];
    __shared__ unsigned sbB[64][2];

    int tid = threadIdx.x;
    int tx = tid & 15, ty = tid >> 4;
    if (tid < 128) { sbA[tid>>1][tid&1] = 0u; sbB[tid>>1][tid&1] = 0u; }

    float acc[4][4] = {};
    int lr = tid >> 2, lkq = tid & 3;
    for (int k0 = 0; k0 < HID; k0 += 16) {
        float4 v = *(const float4*)(embed + (size_t)(i0+lr)*HID + k0 + lkq*4);
        Ei[lkq*4+0][lr] = v.x; Ei[lkq*4+1][lr] = v.y;
        Ei[lkq*4+2][lr] = v.z; Ei[lkq*4+3][lr] = v.w;
        float4 w = *(const float4*)(embed + (size_t)(j0+lr)*HID + k0 + lkq*4);
        Ej[lkq*4+0][lr] = w.x; Ej[lkq*4+1][lr] = w.y;
        Ej[lkq*4+2][lr] = w.z; Ej[lkq*4+3][lr] = w.w;
        __syncthreads();
        #pragma unroll
        for (int kk = 0; kk < 16; kk++) {
            float4 av = *(float4*)&Ei[kk][ty*4];
            float4 bv = *(float4*)&Ej[kk][tx*4];
            float ra[4] = {av.x, av.y, av.z, av.w};
            float rb[4] = {bv.x, bv.y, bv.z, bv.w};
            #pragma unroll
            for (int a = 0; a < 4; a++)
                #pragma unroll
                for (int b = 0; b < 4; b++)
                    acc[a][b] += ra[a] * rb[b];
        }
        __syncthreads();
    }

    float invi[4], invj[4];
    #pragma unroll
    for (int a = 0; a < 4; a++) invi[a] = d_invn[i0 + ty*4 + a];
    #pragma unroll
    for (int b = 0; b < 4; b++) invj[b] = d_invn[j0 + tx*4 + b];

    bool bit[4][4];
    #pragma unroll
    for (int a = 0; a < 4; a++)
        #pragma unroll
        for (int b = 0; b < 4; b++)
            bit[a][b] = (acc[a][b] * invi[a] * invj[b]) > 0.5f;

    #pragma unroll
    for (int a = 0; a < 4; a++) {
        unsigned m = 0;
        #pragma unroll
        for (int b = 0; b < 4; b++) if (bit[a][b]) m |= (1u << b);
        if (m) atomicOr(&sbA[ty*4+a][(tx*4) >> 5], m << ((tx*4) & 31));
    }
    #pragma unroll
    for (int b = 0; b < 4; b++) {
        unsigned m = 0;
        #pragma unroll
        for (int a = 0; a < 4; a++) if (bit[a][b]) m |= (1u << a);
        if (m) atomicOr(&sbB[tx*4+b][(ty*4) >> 5], m << ((ty*4) & 31));
    }
    __syncthreads();

    if (tid < 128) {
        int r = tid >> 1, w = tid & 1;
        d_maskbits[(size_t)(i0+r)*(Nn/32) + (j0>>5) + w] = sbA[r][w];
        if (bx != by)
            d_maskbits[(size_t)(j0+r)*(Nn/32) + (i0>>5) + w] = sbB[r][w];
    }
}

// ---------------- kernel 3: CSR build, one WARP per row (order-preserving) ----
__global__ __launch_bounds__(256) void csr_kernel() {
    int gw = (blockIdx.x*blockDim.x + threadIdx.x) >> 5;   // row index
    int lane = threadIdx.x & 31;
    if (gw >= Nn) return;
    unsigned word = d_maskbits[(size_t)gw*(Nn/32) + lane];  // 32 words = full row
    int cnt = __popc(word);
    // inclusive warp scan of counts
    int pre = cnt;
    #pragma unroll
    for (int off = 1; off < 32; off <<= 1) {
        int n = __shfl_up_sync(0xFFFFFFFFu, pre, off);
        if (lane >= off) pre += n;
    }
    int idx = pre - cnt;                                    // exclusive prefix
    while (word) {
        int b = __ffs(word) - 1;
        word &= word - 1;
        d_nbr[(size_t)gw*Nn + idx++] = lane*32 + b;
    }
    if (lane == 31) d_deg[gw] = pre;
}

// ---------------- Wf = Wp@W1 (+ bias row bf = bp@W1) ----------------
__global__ __launch_bounds__(HID) void wf_kernel(const float* __restrict__ Wp,
                                                 const float* __restrict__ bp,
                                                 const float* __restrict__ W1) {
    __shared__ float srow[HID];
    int r = blockIdx.x, c = threadIdx.x;
    const float* src = (r < INF_) ? (Wp + (size_t)r*HID) : bp;
    srow[c] = src[c];
    __syncthreads();
    float acc = 0.f;
    #pragma unroll 8
    for (int k = 0; k < HID; k++)
        acc += srow[k] * W1[(size_t)k*HID + c];
    if (r < INF_) d_Wf[(size_t)r*HID + c] = acc;
    else          d_bf[c] = acc;
}

// ---------------- fp32 tiled GEMM: C = A[MxK] @ B[KxN] (+bias) ------
#define BM 128
#define BN 64
#define BK 16
__global__ __launch_bounds__(256) void gemm_kernel(const float* __restrict__ A,
                                                   const float* __restrict__ Bm,
                                                   const float* __restrict__ bias,
                                                   float* __restrict__ Cm,
                                                   int M, int N, int K) {
    __shared__ float As[BK][BM];
    __shared__ float Bs[BK][BN];
    int tid = threadIdx.x;
    int tx = tid & 15, ty = tid >> 4;
    int row0 = blockIdx.y * BM, col0 = blockIdx.x * BN;

    float acc[8][4] = {};

    for (int k0 = 0; k0 < K; k0 += BK) {
        #pragma unroll
        for (int i = 0; i < 2; i++) {
            int idx = tid*2 + i;
            int r = idx >> 2, kq = idx & 3;
            float4 v = *(const float4*)(A + (size_t)(row0 + r)*K + k0 + kq*4);
            As[kq*4+0][r] = v.x; As[kq*4+1][r] = v.y;
            As[kq*4+2][r] = v.z; As[kq*4+3][r] = v.w;
        }
        {
            int kk = tid >> 4, cq = tid & 15;
            *(float4*)&Bs[kk][cq*4] =
                *(const float4*)(Bm + (size_t)(k0+kk)*N + col0 + cq*4);
        }
        __syncthreads();
        #pragma unroll
        for (int kk = 0; kk < BK; kk++) {
            float4 a0 = *(float4*)&As[kk][ty*8];
            float4 a1 = *(float4*)&As[kk][ty*8+4];
            float4 b0 = *(float4*)&Bs[kk][tx*4];
            float ra[8] = {a0.x,a0.y,a0.z,a0.w,a1.x,a1.y,a1.z,a1.w};
            float rb[4] = {b0.x,b0.y,b0.z,b0.w};
            #pragma unroll
            for (int a = 0; a < 8; a++)
                #pragma unroll
                for (int b = 0; b < 4; b++)
                    acc[a][b] += ra[a] * rb[b];
        }
        __syncthreads();
    }

    float4 bv = make_float4(0.f, 0.f, 0.f, 0.f);
    if (bias) bv = *(const float4*)(bias + col0 + tx*4);
    #pragma unroll
    for (int a = 0; a < 8; a++) {
        int r = row0 + ty*8 + a;
        float4 o;
        o.x = acc[a][0] + bv.x;
        o.y = acc[a][1] + bv.y;
        o.z = acc[a][2] + bv.z;
        o.w = acc[a][3] + bv.w;
        *(float4*)(Cm + (size_t)r*N + col0 + tx*4) = o;
    }
}

// ---------------- per-row src/dst attention logits ----------------
template <int C, int Dd>
__global__ void srcdst_kernel(const float* __restrict__ g,
                              const float* __restrict__ a_src,
                              const float* __restrict__ a_dst,
                              float* __restrict__ asrc,
                              float* __restrict__ adst) {
    __shared__ float ss[C], sd[C];
    int row = blockIdx.x, c = threadIdx.x;
    float gv = g[(size_t)row*C + c];
    ss[c] = gv * a_src[c];
    sd[c] = gv * a_dst[c];
    __syncthreads();
    for (int st = Dd/2; st > 0; st >>= 1) {
        if ((c & (Dd-1)) < st) { ss[c] += ss[c+st]; sd[c] += sd[c+st]; }
        __syncthreads();
    }
    if ((c & (Dd-1)) == 0) {
        int h = c / Dd;
        asrc[row*Hh + h] = ss[c];
        adst[row*Hh + h] = sd[c];
    }
}

// ---------------- sparse GAT attention (one block per (b,i) row) ----------------
template <int C, int Dd, bool RELU>
__global__ void attn_kernel(const float* __restrict__ g,
                            const float* __restrict__ asrc,
                            const float* __restrict__ adst,
                            const float* __restrict__ bias,
                            float* __restrict__ out) {
    __shared__ int   snbr[Nn];
    __shared__ float sw[Nn*Hh];
    __shared__ float sadst[Hh], srZ[Hh];
    int row = blockIdx.x;
    int b = row >> 10;
    int i = row & (Nn-1);
    int tid = threadIdx.x;
    int deg = d_deg[i];
    for (int k = tid; k < deg; k += C) snbr[k] = d_nbr[(size_t)i*Nn + k];
    if (tid < Hh) sadst[tid] = adst[row*Hh + tid];
    __syncthreads();
    for (int idx = tid; idx < deg*Hh; idx += C) {
        int k = idx >> 2, h = idx & 3;
        float v = sadst[h] + asrc[(b*Nn + snbr[k])*Hh + h];
        sw[idx] = (v >= 0.f) ? v : NEG_SLOPE * v;
    }
    __syncthreads();
    if (tid < Hh) {
        float m = -1e30f;
        for (int k = 0; k < deg; k++) m = fmaxf(m, sw[k*Hh + tid]);
        float Z = 0.f;
        for (int k = 0; k < deg; k++) {
            float p = expf(sw[k*Hh + tid] - m);
            sw[k*Hh + tid] = p;
            Z += p;
        }
        srZ[tid] = 1.f / Z;
    }
    __syncthreads();
    int h = tid / Dd;
    float acc = 0.f;
    if (deg > 0) {
        for (int k = 0; k < deg; k++)
            acc += sw[k*Hh + h] * g[(size_t)(b*Nn + snbr[k])*C + tid];
        acc *= srZ[h];
    } else {
        for (int j = 0; j < Nn; j++)
            acc += g[(size_t)(b*Nn + j)*C + tid];
        acc *= (1.f / Nn);
    }
    float o = acc + bias[tid];
    if (RELU) o = fmaxf(o, 0.f);
    out[(size_t)row*C + tid] = o;
}

// ---------------- launch (forked graph: adjacency || projection) ----------------
static cudaStream_t g_s2 = nullptr;
static cudaEvent_t  g_evFork = nullptr, g_evJoin = nullptr;

extern "C" void kernel_launch(void* const* d_in, const int* in_sizes, int n_in,
                              void* d_out, int out_size) {
    const float* x      = (const float*)d_in[0];
    const float* embed  = (const float*)d_in[1];
    const float* Wp     = (const float*)d_in[2];
    const float* bp     = (const float*)d_in[3];
    const float* W1     = (const float*)d_in[4];
    const float* a_src1 = (const float*)d_in[5];
    const float* a_dst1 = (const float*)d_in[6];
    const float* b1     = (const float*)d_in[7];
    const float* W2     = (const float*)d_in[8];
    const float* a_src2 = (const float*)d_in[9];
    const float* a_dst2 = (const float*)d_in[10];
    const float* b2     = (const float*)d_in[11];
    float* out = (float*)d_out;

    // one-time handle creation (host objects only; no device memory)
    if (g_s2 == nullptr) {
        cudaStreamCreateWithFlags(&g_s2, cudaStreamNonBlocking);
        cudaEventCreateWithFlags(&g_evFork, cudaEventDisableTiming);
        cudaEventCreateWithFlags(&g_evJoin, cudaEventDisableTiming);
    }

    float *g1, *h1, *g2, *Wf, *bf, *asrc1p, *adst1p, *asrc2p, *adst2p;
    cudaGetSymbolAddress((void**)&g1, d_g1);
    cudaGetSymbolAddress((void**)&h1, d_h1);
    cudaGetSymbolAddress((void**)&g2, d_g2);
    cudaGetSymbolAddress((void**)&Wf, d_Wf);
    cudaGetSymbolAddress((void**)&bf, d_bf);
    cudaGetSymbolAddress((void**)&asrc1p, d_asrc1);
    cudaGetSymbolAddress((void**)&adst1p, d_adst1);
    cudaGetSymbolAddress((void**)&asrc2p, d_asrc2);
    cudaGetSymbolAddress((void**)&adst2p, d_adst2);

    const int M = Bq * Nn;   // 8192

    // ---- fork: adjacency chain on side stream ----
    cudaEventRecord(g_evFork, 0);
    cudaStreamWaitEvent(g_s2, g_evFork, 0);
    invnorm_kernel<<<Nn, HID, 0, g_s2>>>(embed);
    mask_kernel<<<(Nn/64)*((Nn/64)+1)/2, 256, 0, g_s2>>>(embed);
    csr_kernel<<<(Nn*32 + 255)/256, 256, 0, g_s2>>>();
    cudaEventRecord(g_evJoin, g_s2);

    // ---- main stream: projection chain ----
    wf_kernel<<<INF_ + 1, HID>>>(Wp, bp, W1);
    gemm_kernel<<<dim3(HID/BN, M/BM), 256>>>(x, Wf, bf, g1, M, HID, INF_);
    srcdst_kernel<HID, D1><<<M, HID>>>(g1, a_src1, a_dst1, asrc1p, adst1p);

    // ---- join before attention (needs d_deg/d_nbr) ----
    cudaStreamWaitEvent(0, g_evJoin, 0);

    // layer 1
    attn_kernel<HID, D1, true><<<M, HID>>>(g1, asrc1p, adst1p, b1, h1);

    // layer 2
    gemm_kernel<<<dim3(OUTD/BN, M/BM), 256>>>(h1, W2, nullptr, g2, M, OUTD, HID);
    srcdst_kernel<OUTD, D2><<<M, OUTD>>>(g2, a_src2, a_dst2, asrc2p, adst2p);
    attn_kernel<OUTD, D2, false><<<M, OUTD>>>(g2, asrc2p, adst2p, b2, out);
}

// round 12
// speedup vs baseline: 2.3652x; 1.0218x over previous
#include <cuda_runtime.h>
#include <cuda_bf16.h>
#include <math.h>

// Problem constants (fixed by setup_inputs)
#define Bq   8
#define Nn   1024
#define INF_ 64
#define HID  256
#define OUTD 128
#define Hh   4
#define D1   (HID/Hh)   // 64
#define D2   (OUTD/Hh)  // 32
#define NEG_SLOPE 0.2f

// Wf split-K config
#define WF_KC 32            // number of K chunks
#define WF_KW (HID/WF_KC)   // 8 k-values per chunk
#define WF_ROWS (INF_ + 1)  // 64 Wp rows + 1 bias row

// ---------------- scratch (device globals; no allocations) ----------------
__device__ float     d_g1[Bq*Nn*HID];      // 8 MB
__device__ float     d_h1[Bq*Nn*HID];      // 8 MB
__device__ float     d_g2[Bq*Nn*OUTD];     // 4 MB
__device__ float     d_Wf[INF_*HID];
__device__ float     d_bf[HID];
__device__ float     d_wfpart[WF_KC][WF_ROWS][HID];   // 2.1 MB split-K partials
__device__ float     d_invn[Nn];
__device__ unsigned  d_maskbits[Nn*(Nn/32)];
__device__ int       d_nbr[Nn*Nn];         // 4 MB CSR (fixed row stride Nn)
__device__ int       d_deg[Nn];
__device__ float     d_asrc1[Bq*Nn*Hh], d_adst1[Bq*Nn*Hh];
__device__ float     d_asrc2[Bq*Nn*Hh], d_adst2[Bq*Nn*Hh];

// ---------------- kernel 1: row inverse norms of embed ----------------
__global__ void invnorm_kernel(const float* __restrict__ embed) {
    __shared__ float s[HID];
    int i = blockIdx.x, t = threadIdx.x;
    float e = embed[i*HID + t];
    s[t] = e * e;
    __syncthreads();
    for (int st = HID/2; st > 0; st >>= 1) {
        if (t < st) s[t] += s[t + st];
        __syncthreads();
    }
    if (t == 0) d_invn[i] = rsqrtf(s[0]);
}

// ---------------- kernel 2: symmetric mask bits (ne@ne.T > 0.5) ----------------
__global__ __launch_bounds__(256) void mask_kernel(const float* __restrict__ embed) {
    // decode triangular block index -> (by=q, bx=p) with p>=q
    int id = blockIdx.x;
    int p = (int)((sqrtf(8.f*(float)id + 1.f) - 1.f) * 0.5f);
    while ((p+1)*(p+2)/2 <= id) p++;
    while (p*(p+1)/2 > id) p--;
    int q = id - p*(p+1)/2;
    int by = q, bx = p;
    int i0 = by*64, j0 = bx*64;

    __shared__ float Ei[16][64];
    __shared__ float Ej[16][64];
    __shared__ unsigned sbA[64][2];
    __shared__ unsigned sbB[64][2];

    int tid = threadIdx.x;
    int tx = tid & 15, ty = tid >> 4;
    if (tid < 128) { sbA[tid>>1][tid&1] = 0u; sbB[tid>>1][tid&1] = 0u; }

    float acc[4][4] = {};
    int lr = tid >> 2, lkq = tid & 3;
    for (int k0 = 0; k0 < HID; k0 += 16) {
        float4 v = *(const float4*)(embed + (size_t)(i0+lr)*HID + k0 + lkq*4);
        Ei[lkq*4+0][lr] = v.x; Ei[lkq*4+1][lr] = v.y;
        Ei[lkq*4+2][lr] = v.z; Ei[lkq*4+3][lr] = v.w;
        float4 w = *(const float4*)(embed + (size_t)(j0+lr)*HID + k0 + lkq*4);
        Ej[lkq*4+0][lr] = w.x; Ej[lkq*4+1][lr] = w.y;
        Ej[lkq*4+2][lr] = w.z; Ej[lkq*4+3][lr] = w.w;
        __syncthreads();
        #pragma unroll
        for (int kk = 0; kk < 16; kk++) {
            float4 av = *(float4*)&Ei[kk][ty*4];
            float4 bv = *(float4*)&Ej[kk][tx*4];
            float ra[4] = {av.x, av.y, av.z, av.w};
            float rb[4] = {bv.x, bv.y, bv.z, bv.w};
            #pragma unroll
            for (int a = 0; a < 4; a++)
                #pragma unroll
                for (int b = 0; b < 4; b++)
                    acc[a][b] += ra[a] * rb[b];
        }
        __syncthreads();
    }

    float invi[4], invj[4];
    #pragma unroll
    for (int a = 0; a < 4; a++) invi[a] = d_invn[i0 + ty*4 + a];
    #pragma unroll
    for (int b = 0; b < 4; b++) invj[b] = d_invn[j0 + tx*4 + b];

    bool bit[4][4];
    #pragma unroll
    for (int a = 0; a < 4; a++)
        #pragma unroll
        for (int b = 0; b < 4; b++)
            bit[a][b] = (acc[a][b] * invi[a] * invj[b]) > 0.5f;

    #pragma unroll
    for (int a = 0; a < 4; a++) {
        unsigned m = 0;
        #pragma unroll
        for (int b = 0; b < 4; b++) if (bit[a][b]) m |= (1u << b);
        if (m) atomicOr(&sbA[ty*4+a][(tx*4) >> 5], m << ((tx*4) & 31));
    }
    #pragma unroll
    for (int b = 0; b < 4; b++) {
        unsigned m = 0;
        #pragma unroll
        for (int a = 0; a < 4; a++) if (bit[a][b]) m |= (1u << a);
        if (m) atomicOr(&sbB[tx*4+b][(ty*4) >> 5], m << ((ty*4) & 31));
    }
    __syncthreads();

    if (tid < 128) {
        int r = tid >> 1, w = tid & 1;
        d_maskbits[(size_t)(i0+r)*(Nn/32) + (j0>>5) + w] = sbA[r][w];
        if (bx != by)
            d_maskbits[(size_t)(j0+r)*(Nn/32) + (i0>>5) + w] = sbB[r][w];
    }
}

// ---------------- kernel 3: CSR build, one WARP per row (order-preserving) ----
__global__ __launch_bounds__(256) void csr_kernel() {
    int gw = (blockIdx.x*blockDim.x + threadIdx.x) >> 5;   // row index
    int lane = threadIdx.x & 31;
    if (gw >= Nn) return;
    unsigned word = d_maskbits[(size_t)gw*(Nn/32) + lane];  // 32 words = full row
    int cnt = __popc(word);
    // inclusive warp scan of counts
    int pre = cnt;
    #pragma unroll
    for (int off = 1; off < 32; off <<= 1) {
        int n = __shfl_up_sync(0xFFFFFFFFu, pre, off);
        if (lane >= off) pre += n;
    }
    int idx = pre - cnt;                                    // exclusive prefix
    while (word) {
        int b = __ffs(word) - 1;
        word &= word - 1;
        d_nbr[(size_t)gw*Nn + idx++] = lane*32 + b;
    }
    if (lane == 31) d_deg[gw] = pre;
}

// ---------------- Wf split-K stage 1: partial[kc][r][c] ----------------
// One block per K-chunk of WF_KW. Thread owns column c: loads its WF_KW W1
// values once (coalesced), reuses them across all WF_ROWS rows from smem.
__global__ __launch_bounds__(HID) void wf_part_kernel(const float* __restrict__ Wp,
                                                      const float* __restrict__ bp,
                                                      const float* __restrict__ W1) {
    __shared__ float sWp[WF_ROWS][WF_KW];
    int kc = blockIdx.x;
    int c  = threadIdx.x;
    int k0 = kc * WF_KW;

    // stage Wp chunk (+ bias row) : WF_ROWS*WF_KW = 520 elements
    for (int idx = c; idx < WF_ROWS*WF_KW; idx += HID) {
        int r = idx / WF_KW, k = idx % WF_KW;
        sWp[r][k] = (r < INF_) ? Wp[(size_t)r*HID + k0 + k] : bp[k0 + k];
    }
    __syncthreads();

    // W1 chunk for this column, in registers
    float w1[WF_KW];
    #pragma unroll
    for (int k = 0; k < WF_KW; k++)
        w1[k] = W1[(size_t)(k0 + k)*HID + c];

    #pragma unroll 4
    for (int r = 0; r < WF_ROWS; r++) {
        float acc = 0.f;
        #pragma unroll
        for (int k = 0; k < WF_KW; k++)
            acc += sWp[r][k] * w1[k];
        d_wfpart[kc][r][c] = acc;
    }
}

// ---------------- Wf split-K stage 2: fixed-order reduce ----------------
__global__ __launch_bounds__(HID) void wf_reduce_kernel() {
    int r = blockIdx.x;     // 0..WF_ROWS-1
    int c = threadIdx.x;
    float acc = 0.f;
    #pragma unroll
    for (int kc = 0; kc < WF_KC; kc++)
        acc += d_wfpart[kc][r][c];
    if (r < INF_) d_Wf[(size_t)r*HID + c] = acc;
    else          d_bf[c] = acc;
}

// ---------------- fp32 tiled GEMM: C = A[MxK] @ B[KxN] (+bias) ------
#define BM 128
#define BN 64
#define BK 16
__global__ __launch_bounds__(256) void gemm_kernel(const float* __restrict__ A,
                                                   const float* __restrict__ Bm,
                                                   const float* __restrict__ bias,
                                                   float* __restrict__ Cm,
                                                   int M, int N, int K) {
    __shared__ float As[BK][BM];
    __shared__ float Bs[BK][BN];
    int tid = threadIdx.x;
    int tx = tid & 15, ty = tid >> 4;
    int row0 = blockIdx.y * BM, col0 = blockIdx.x * BN;

    float acc[8][4] = {};

    for (int k0 = 0; k0 < K; k0 += BK) {
        #pragma unroll
        for (int i = 0; i < 2; i++) {
            int idx = tid*2 + i;
            int r = idx >> 2, kq = idx & 3;
            float4 v = *(const float4*)(A + (size_t)(row0 + r)*K + k0 + kq*4);
            As[kq*4+0][r] = v.x; As[kq*4+1][r] = v.y;
            As[kq*4+2][r] = v.z; As[kq*4+3][r] = v.w;
        }
        {
            int kk = tid >> 4, cq = tid & 15;
            *(float4*)&Bs[kk][cq*4] =
                *(const float4*)(Bm + (size_t)(k0+kk)*N + col0 + cq*4);
        }
        __syncthreads();
        #pragma unroll
        for (int kk = 0; kk < BK; kk++) {
            float4 a0 = *(float4*)&As[kk][ty*8];
            float4 a1 = *(float4*)&As[kk][ty*8+4];
            float4 b0 = *(float4*)&Bs[kk][tx*4];
            float ra[8] = {a0.x,a0.y,a0.z,a0.w,a1.x,a1.y,a1.z,a1.w};
            float rb[4] = {b0.x,b0.y,b0.z,b0.w};
            #pragma unroll
            for (int a = 0; a < 8; a++)
                #pragma unroll
                for (int b = 0; b < 4; b++)
                    acc[a][b] += ra[a] * rb[b];
        }
        __syncthreads();
    }

    float4 bv = make_float4(0.f, 0.f, 0.f, 0.f);
    if (bias) bv = *(const float4*)(bias + col0 + tx*4);
    #pragma unroll
    for (int a = 0; a < 8; a++) {
        int r = row0 + ty*8 + a;
        float4 o;
        o.x = acc[a][0] + bv.x;
        o.y = acc[a][1] + bv.y;
        o.z = acc[a][2] + bv.z;
        o.w = acc[a][3] + bv.w;
        *(float4*)(Cm + (size_t)r*N + col0 + tx*4) = o;
    }
}

// ---------------- per-row src/dst attention logits ----------------
template <int C, int Dd>
__global__ void srcdst_kernel(const float* __restrict__ g,
                              const float* __restrict__ a_src,
                              const float* __restrict__ a_dst,
                              float* __restrict__ asrc,
                              float* __restrict__ adst) {
    __shared__ float ss[C], sd[C];
    int row = blockIdx.x, c = threadIdx.x;
    float gv = g[(size_t)row*C + c];
    ss[c] = gv * a_src[c];
    sd[c] = gv * a_dst[c];
    __syncthreads();
    for (int st = Dd/2; st > 0; st >>= 1) {
        if ((c & (Dd-1)) < st) { ss[c] += ss[c+st]; sd[c] += sd[c+st]; }
        __syncthreads();
    }
    if ((c & (Dd-1)) == 0) {
        int h = c / Dd;
        asrc[row*Hh + h] = ss[c];
        adst[row*Hh + h] = sd[c];
    }
}

// ---------------- sparse GAT attention (one block per (b,i) row) ----------------
template <int C, int Dd, bool RELU>
__global__ void attn_kernel(const float* __restrict__ g,
                            const float* __restrict__ asrc,
                            const float* __restrict__ adst,
                            const float* __restrict__ bias,
                            float* __restrict__ out) {
    __shared__ int   snbr[Nn];
    __shared__ float sw[Nn*Hh];
    __shared__ float sadst[Hh], srZ[Hh];
    int row = blockIdx.x;
    int b = row >> 10;
    int i = row & (Nn-1);
    int tid = threadIdx.x;
    int deg = d_deg[i];
    for (int k = tid; k < deg; k += C) snbr[k] = d_nbr[(size_t)i*Nn + k];
    if (tid < Hh) sadst[tid] = adst[row*Hh + tid];
    __syncthreads();
    for (int idx = tid; idx < deg*Hh; idx += C) {
        int k = idx >> 2, h = idx & 3;
        float v = sadst[h] + asrc[(b*Nn + snbr[k])*Hh + h];
        sw[idx] = (v >= 0.f) ? v : NEG_SLOPE * v;
    }
    __syncthreads();
    if (tid < Hh) {
        float m = -1e30f;
        for (int k = 0; k < deg; k++) m = fmaxf(m, sw[k*Hh + tid]);
        float Z = 0.f;
        for (int k = 0; k < deg; k++) {
            float p = expf(sw[k*Hh + tid] - m);
            sw[k*Hh + tid] = p;
            Z += p;
        }
        srZ[tid] = 1.f / Z;
    }
    __syncthreads();
    int h = tid / Dd;
    float acc = 0.f;
    if (deg > 0) {
        for (int k = 0; k < deg; k++)
            acc += sw[k*Hh + h] * g[(size_t)(b*Nn + snbr[k])*C + tid];
        acc *= srZ[h];
    } else {
        for (int j = 0; j < Nn; j++)
            acc += g[(size_t)(b*Nn + j)*C + tid];
        acc *= (1.f / Nn);
    }
    float o = acc + bias[tid];
    if (RELU) o = fmaxf(o, 0.f);
    out[(size_t)row*C + tid] = o;
}

// ---------------- launch (forked graph: adjacency || projection) ----------------
static cudaStream_t g_s2 = nullptr;
static cudaEvent_t  g_evFork = nullptr, g_evJoin = nullptr;

extern "C" void kernel_launch(void* const* d_in, const int* in_sizes, int n_in,
                              void* d_out, int out_size) {
    const float* x      = (const float*)d_in[0];
    const float* embed  = (const float*)d_in[1];
    const float* Wp     = (const float*)d_in[2];
    const float* bp     = (const float*)d_in[3];
    const float* W1     = (const float*)d_in[4];
    const float* a_src1 = (const float*)d_in[5];
    const float* a_dst1 = (const float*)d_in[6];
    const float* b1     = (const float*)d_in[7];
    const float* W2     = (const float*)d_in[8];
    const float* a_src2 = (const float*)d_in[9];
    const float* a_dst2 = (const float*)d_in[10];
    const float* b2     = (const float*)d_in[11];
    float* out = (float*)d_out;

    // one-time handle creation (host objects only; no device memory)
    if (g_s2 == nullptr) {
        cudaStreamCreateWithFlags(&g_s2, cudaStreamNonBlocking);
        cudaEventCreateWithFlags(&g_evFork, cudaEventDisableTiming);
        cudaEventCreateWithFlags(&g_evJoin, cudaEventDisableTiming);
    }

    float *g1, *h1, *g2, *Wf, *bf, *asrc1p, *adst1p, *asrc2p, *adst2p;
    cudaGetSymbolAddress((void**)&g1, d_g1);
    cudaGetSymbolAddress((void**)&h1, d_h1);
    cudaGetSymbolAddress((void**)&g2, d_g2);
    cudaGetSymbolAddress((void**)&Wf, d_Wf);
    cudaGetSymbolAddress((void**)&bf, d_bf);
    cudaGetSymbolAddress((void**)&asrc1p, d_asrc1);
    cudaGetSymbolAddress((void**)&adst1p, d_adst1);
    cudaGetSymbolAddress((void**)&asrc2p, d_asrc2);
    cudaGetSymbolAddress((void**)&adst2p, d_adst2);

    const int M = Bq * Nn;   // 8192

    // ---- fork: adjacency chain on side stream ----
    cudaEventRecord(g_evFork, 0);
    cudaStreamWaitEvent(g_s2, g_evFork, 0);
    invnorm_kernel<<<Nn, HID, 0, g_s2>>>(embed);
    mask_kernel<<<(Nn/64)*((Nn/64)+1)/2, 256, 0, g_s2>>>(embed);
    csr_kernel<<<(Nn*32 + 255)/256, 256, 0, g_s2>>>();
    cudaEventRecord(g_evJoin, g_s2);

    // ---- main stream: projection chain (split-K Wf) ----
    wf_part_kernel<<<WF_KC, HID>>>(Wp, bp, W1);
    wf_reduce_kernel<<<WF_ROWS, HID>>>();
    gemm_kernel<<<dim3(HID/BN, M/BM), 256>>>(x, Wf, bf, g1, M, HID, INF_);
    srcdst_kernel<HID, D1><<<M, HID>>>(g1, a_src1, a_dst1, asrc1p, adst1p);

    // ---- join before attention (needs d_deg/d_nbr) ----
    cudaStreamWaitEvent(0, g_evJoin, 0);

    // layer 1
    attn_kernel<HID, D1, true><<<M, HID>>>(g1, asrc1p, adst1p, b1, h1);

    // layer 2
    gemm_kernel<<<dim3(OUTD/BN, M/BM), 256>>>(h1, W2, nullptr, g2, M, OUTD, HID);
    srcdst_kernel<OUTD, D2><<<M, OUTD>>>(g2, a_src2, a_dst2, asrc2p, adst2p);
    attn_kernel<OUTD, D2, false><<<M, OUTD>>>(g2, asrc2p, adst2p, b2, out);
}